// round 14
// baseline (speedup 1.0000x reference)
#include <cuda_runtime.h>
#include <cuda_fp16.h>
#include <math.h>
#include <stdint.h>

// ---------------------------------------------------------------------------
// TransformerBlock: persistent (divide-free) fp16 m16n8k16 GEMMs + fp16 flash
// attention (P-in-register, exp2 softmax). Merged wtr+ln1 prep launch.
// Shapes: B=4, T=2048 (BT=8192), C=1024, H=16, D=64, DFF=4096
// ---------------------------------------------------------------------------

#define BT   8192
#define C    1024
#define C3   3072
#define H    16
#define D    64
#define DFF  4096
#define T    2048
#define EPS  1e-5f
#define NPERS 296

// Scratch (__device__ globals; no allocations allowed)
__device__ __half g_ln[BT * C];
__device__ __half g_qkv[BT * C3];
__device__ __half g_attn[BT * C];
__device__ __half g_h1[BT * DFF];
// fp16 TRANSPOSED weights: [N][K]
#define WT_QKV  0
#define WT_PROJ (WT_QKV + C * C3)
#define WT_W1   (WT_PROJ + C * C)
#define WT_W2   (WT_W1 + C * DFF)
#define WT_TOT  (WT_W2 + DFF * C)
__device__ __half g_wt[WT_TOT];

// ---------------------------------------------------------------------------
// Helpers
// ---------------------------------------------------------------------------
__device__ __forceinline__ uint32_t smem_u32(const void* p) {
    uint32_t a;
    asm("{ .reg .u64 t; cvta.to.shared.u64 t, %1; cvt.u32.u64 %0, t; }" : "=r"(a) : "l"(p));
    return a;
}
__device__ __forceinline__ void cp_async16(uint32_t dst, const void* src) {
    asm volatile("cp.async.ca.shared.global [%0], [%1], 16;" :: "r"(dst), "l"(src) : "memory");
}
__device__ __forceinline__ void cp_commit() {
    asm volatile("cp.async.commit_group;" ::: "memory");
}
template<int N>
__device__ __forceinline__ void cp_wait() {
    asm volatile("cp.async.wait_group %0;" :: "n"(N) : "memory");
}
__device__ __forceinline__ void ldsm_x4(uint32_t& r0, uint32_t& r1, uint32_t& r2, uint32_t& r3,
                                        uint32_t addr) {
    asm volatile("ldmatrix.sync.aligned.m8n8.x4.shared.b16 {%0,%1,%2,%3}, [%4];"
                 : "=r"(r0), "=r"(r1), "=r"(r2), "=r"(r3) : "r"(addr));
}
__device__ __forceinline__ void ldsm_x4_trans(uint32_t& r0, uint32_t& r1, uint32_t& r2, uint32_t& r3,
                                              uint32_t addr) {
    asm volatile("ldmatrix.sync.aligned.m8n8.x4.trans.shared.b16 {%0,%1,%2,%3}, [%4];"
                 : "=r"(r0), "=r"(r1), "=r"(r2), "=r"(r3) : "r"(addr));
}
__device__ __forceinline__ void mma_16n8k16(float* d, const uint32_t* a, const uint32_t* b) {
    asm volatile(
        "mma.sync.aligned.m16n8k16.row.col.f32.f16.f16.f32 "
        "{%0,%1,%2,%3}, {%4,%5,%6,%7}, {%8,%9}, {%0,%1,%2,%3};"
        : "+f"(d[0]), "+f"(d[1]), "+f"(d[2]), "+f"(d[3])
        : "r"(a[0]), "r"(a[1]), "r"(a[2]), "r"(a[3]), "r"(b[0]), "r"(b[1]));
}
__device__ __forceinline__ uint32_t pack_h2(float a, float b) {
    __half2 h = __floats2half2_rn(a, b);
    return *(uint32_t*)&h;
}
__device__ __forceinline__ float gelu_exact(float v) {
    return 0.5f * v * (1.0f + erff(v * 0.70710678118654752f));
}

// ---------------------------------------------------------------------------
// LayerNorm row body (shared by prep kernel and ln2 kernel)
// ---------------------------------------------------------------------------
__device__ __forceinline__ void ln_row(
    const float* __restrict__ x, const float* __restrict__ g,
    const float* __restrict__ beta, __half* __restrict__ out, int row, int t)
{
    const float* xr = x + (size_t)row * C;
    float4 xv = *(const float4*)(xr + t * 4);
    float s  = xv.x + xv.y + xv.z + xv.w;
    float s2 = xv.x * xv.x + xv.y * xv.y + xv.z * xv.z + xv.w * xv.w;
    #pragma unroll
    for (int o = 16; o > 0; o >>= 1) {
        s  += __shfl_xor_sync(0xffffffffu, s,  o);
        s2 += __shfl_xor_sync(0xffffffffu, s2, o);
    }
    __shared__ float ss[8], ss2[8];
    int w = t >> 5, lane = t & 31;
    if (lane == 0) { ss[w] = s; ss2[w] = s2; }
    __syncthreads();
    if (w == 0) {
        s  = (lane < 8) ? ss[lane]  : 0.f;
        s2 = (lane < 8) ? ss2[lane] : 0.f;
        #pragma unroll
        for (int o = 4; o > 0; o >>= 1) {
            s  += __shfl_xor_sync(0xffffffffu, s,  o);
            s2 += __shfl_xor_sync(0xffffffffu, s2, o);
        }
        if (lane == 0) { ss[0] = s; ss2[0] = s2; }
    }
    __syncthreads();
    float mu  = ss[0] * (1.0f / C);
    float var = ss2[0] * (1.0f / C) - mu * mu;
    float inv = rsqrtf(var + EPS);
    float4 gv = *(const float4*)(g + t * 4);
    float4 bv = *(const float4*)(beta + t * 4);
    __half2* o = (__half2*)(out + (size_t)row * C + t * 4);
    o[0] = __floats2half2_rn((xv.x - mu) * inv * gv.x + bv.x,
                             (xv.y - mu) * inv * gv.y + bv.y);
    o[1] = __floats2half2_rn((xv.z - mu) * inv * gv.z + bv.z,
                             (xv.w - mu) * inv * gv.w + bv.w);
}

__global__ __launch_bounds__(256) void ln_kernel(
    const float* __restrict__ x, const float* __restrict__ g,
    const float* __restrict__ beta, __half* __restrict__ out)
{
    ln_row(x, g, beta, out, blockIdx.x, threadIdx.x);
}

// ---------------------------------------------------------------------------
// Prep kernel: weight transpose+convert (blocks [0, WTR_GRID)) AND LN1
// (blocks [WTR_GRID, WTR_GRID+BT)). Independent inputs, both memory-bound.
// ---------------------------------------------------------------------------
#define WTR_GRID (768 + 256 + 1024 + 1024)
#define PREP_GRID (WTR_GRID + BT)

__global__ __launch_bounds__(256) void prep_kernel(
    const float* __restrict__ wqkv, const float* __restrict__ wproj,
    const float* __restrict__ w1, const float* __restrict__ w2,
    __half* __restrict__ wt,
    const float* __restrict__ x, const float* __restrict__ ln1_g,
    const float* __restrict__ ln1_b, __half* __restrict__ lnout)
{
    int b = blockIdx.x;
    int t = threadIdx.x;
    if (b >= WTR_GRID) {
        ln_row(x, ln1_g, ln1_b, lnout, b - WTR_GRID, t);
        return;
    }
    const float* in; __half* out; int K, N, local;
    if (b < 768)        { in = wqkv;  out = wt + WT_QKV;  K = C;   N = C3;  local = b; }
    else if (b < 1024)  { in = wproj; out = wt + WT_PROJ; K = C;   N = C;   local = b - 768; }
    else if (b < 2048)  { in = w1;    out = wt + WT_W1;   K = C;   N = DFF; local = b - 1024; }
    else                { in = w2;    out = wt + WT_W2;   K = DFF; N = C;   local = b - 2048; }
    int nX = N >> 6;
    int n0 = (local % nX) * 64, k0 = (local / nX) * 64;

    __shared__ float tile[64][65];
    #pragma unroll
    for (int it = 0; it < 4; it++) {
        int idx = t + it * 256;
        int kr = idx >> 4;
        int nc = (idx & 15) << 2;
        float4 v = *(const float4*)(in + (size_t)(k0 + kr) * N + n0 + nc);
        tile[kr][nc] = v.x; tile[kr][nc + 1] = v.y;
        tile[kr][nc + 2] = v.z; tile[kr][nc + 3] = v.w;
    }
    __syncthreads();
    #pragma unroll
    for (int it = 0; it < 2; it++) {
        int idx = t + it * 256;
        int nr = idx >> 3;
        int kc = (idx & 7) << 3;
        __half h[8];
        #pragma unroll
        for (int i = 0; i < 8; i++) h[i] = __float2half(tile[kc + i][nr]);
        *(uint4*)(out + (size_t)(n0 + nr) * K + k0 + kc) = *(uint4*)h;
    }
}

// ---------------------------------------------------------------------------
// Persistent fp16 GEMM (divide-free): D = A @ Bt^T (+bias)(gelu)(+resid)
// Grid = NPERS; tile coords computed ONCE per tile (outside chunk loop).
// Inner loop identical to R11; last chunk slot prefetches next tile's chunk 0
// (NCH even -> buffer parity consistent). Epilogue overlaps that load.
// ---------------------------------------------------------------------------
#define HSTR 72
#define TILE_BYTES (128 * HSTR * 2)
#define STAGE_BYTES (2 * TILE_BYTES)
#define GEMM_SMEM_BYTES (2 * STAGE_BYTES)

template<int ACT, bool BIAS, bool RESID, bool OUT_HALF>
__global__ __launch_bounds__(128, 2) void gemm_fp16(
    const __half* __restrict__ A, const __half* __restrict__ Bt,
    const float* __restrict__ bias, const float* __restrict__ resid,
    void* __restrict__ CoutV, int M, int N, int K)
{
    extern __shared__ char smem[];
    int t    = threadIdx.x;
    int lane = t & 31;
    int w    = t >> 5;
    int grp  = lane >> 2;
    int tg   = lane & 3;
    int wm = (w >> 1) * 64;
    int wn = (w & 1) * 64;

    uint32_t smemBase = smem_u32(smem);

    int lrow = lane & 7;
    int lsel = lane >> 3;
    uint32_t a_off = (uint32_t)(((wm + lrow + (lsel & 1) * 8) * HSTR + (lsel >> 1) * 8) * 2);
    uint32_t b_off = (uint32_t)(((wn + lrow + (lsel >> 1) * 8) * HSTR + (lsel & 1) * 8) * 2)
                   + (uint32_t)TILE_BYTES;

    const int nTilesX = N >> 7;
    const int nTiles  = (M >> 7) * nTilesX;
    int tile = blockIdx.x;
    if (tile >= nTiles) return;
    int bm = (tile / nTilesX) * 128;
    int bn = (tile % nTilesX) * 128;
    const int NCH = K >> 6;   // even for all call sites

    auto load_chunk = [&](int lbm, int lbn, int c, int buf) {
        uint32_t base = smemBase + (uint32_t)(buf * STAGE_BYTES);
        int k0 = c << 6;
        #pragma unroll
        for (int it = 0; it < 8; it++) {
            int idx   = t + it * 128;
            int row   = idx >> 3;
            int col16 = idx & 7;
            uint32_t soff = (uint32_t)(row * (HSTR * 2) + col16 * 16);
            cp_async16(base + soff,
                       A + (size_t)(lbm + row) * K + k0 + col16 * 8);
            cp_async16(base + (uint32_t)TILE_BYTES + soff,
                       Bt + (size_t)(lbn + row) * K + k0 + col16 * 8);
        }
        cp_commit();
    };

    load_chunk(bm, bn, 0, 0);

    float acc[4][8][4];

    while (true) {
        // next-tile coords computed ONCE per tile (single divide per ~5 tiles)
        int ntile = tile + NPERS;
        bool hasNext = ntile < nTiles;
        int nbm = 0, nbn = 0;
        if (hasNext) { nbm = (ntile / nTilesX) * 128; nbn = (ntile % nTilesX) * 128; }

        #pragma unroll
        for (int mi = 0; mi < 4; mi++)
            #pragma unroll
            for (int ni = 0; ni < 8; ni++)
                #pragma unroll
                for (int r = 0; r < 4; r++) acc[mi][ni][r] = 0.f;

        for (int c = 0; c < NCH; c++) {
            cp_wait<0>();
            __syncthreads();
            if (c + 1 < NCH)      load_chunk(bm, bn, c + 1, (c + 1) & 1);
            else if (hasNext)     load_chunk(nbm, nbn, 0, 0);   // NCH even -> buf 0

            uint32_t base = smemBase + (uint32_t)((c & 1) * STAGE_BYTES);
            uint32_t aB = base + a_off;
            uint32_t bB = base + b_off;

            #pragma unroll
            for (int ks = 0; ks < 4; ks++) {
                uint32_t kOff = (uint32_t)(ks * 32);
                uint32_t af[4][4], bf[8][2];
                #pragma unroll
                for (int mi = 0; mi < 4; mi++)
                    ldsm_x4(af[mi][0], af[mi][1], af[mi][2], af[mi][3],
                            aB + kOff + (uint32_t)(mi * 16 * HSTR * 2));
                #pragma unroll
                for (int p = 0; p < 4; p++)
                    ldsm_x4(bf[2*p][0], bf[2*p][1], bf[2*p+1][0], bf[2*p+1][1],
                            bB + kOff + (uint32_t)(p * 16 * HSTR * 2));
                #pragma unroll
                for (int mi = 0; mi < 4; mi++)
                    #pragma unroll
                    for (int ni = 0; ni < 8; ni++)
                        mma_16n8k16(acc[mi][ni], af[mi], bf[ni]);
            }
        }

        // epilogue (register-only; overlaps next tile's in-flight chunk 0)
        #pragma unroll
        for (int mi = 0; mi < 4; mi++) {
            #pragma unroll
            for (int half = 0; half < 2; half++) {
                int row = bm + wm + mi * 16 + grp + half * 8;
                const float* rrow = RESID ? (resid + (size_t)row * N + bn) : nullptr;
                #pragma unroll
                for (int ni = 0; ni < 8; ni++) {
                    int col = wn + ni * 8 + tg * 2;
                    float v0 = acc[mi][ni][half * 2 + 0];
                    float v1 = acc[mi][ni][half * 2 + 1];
                    if (BIAS) {
                        float2 bb = *(const float2*)(bias + bn + col);
                        v0 += bb.x; v1 += bb.y;
                    }
                    if (ACT == 1) { v0 = gelu_exact(v0); v1 = gelu_exact(v1); }
                    if (RESID) {
                        float2 rr = *(const float2*)(rrow + col);
                        v0 += rr.x; v1 += rr.y;
                    }
                    if (OUT_HALF) {
                        __half* orow = (__half*)CoutV + (size_t)row * N + bn;
                        *(__half2*)(orow + col) = __floats2half2_rn(v0, v1);
                    } else {
                        float* orow = (float*)CoutV + (size_t)row * N + bn;
                        *(float2*)(orow + col) = make_float2(v0, v1);
                    }
                }
            }
        }

        if (!hasNext) break;
        tile = ntile; bm = nbm; bn = nbn;
    }
}

// ---------------------------------------------------------------------------
// Flash attention, fp16 m16n8k16, exp2 softmax (unchanged from R13).
// ---------------------------------------------------------------------------
#define ASTR 72
#define Q_BYTES   (128 * ASTR * 2)
#define KV_BYTES  (64 * ASTR * 2)
#define AST_BYTES (2 * KV_BYTES)
#define ATTN_SMEM_BYTES (Q_BYTES + 3 * AST_BYTES)

__global__ __launch_bounds__(128, 2) void attn_mma_kernel(
    const __half* __restrict__ qkv, __half* __restrict__ out)
{
    extern __shared__ char sm[];
    uint32_t smBase = smem_u32(sm);
    __half* Qs = (__half*)sm;

    int qt = blockIdx.x, h = blockIdx.y, b = blockIdx.z;
    int t = threadIdx.x, lane = t & 31, w = t >> 5;
    int grp = lane >> 2, tg = lane & 3;
    int lrow = lane & 7, lsel = lane >> 3;

    const size_t tok0 = (size_t)b * T;
    const int NCHK = T / 64;

    {
        __half2 sc = __float2half2_rn(0.18033688f);   // 0.125 * log2(e)
        #pragma unroll
        for (int it = 0; it < 8; it++) {
            int idx   = t + it * 128;
            int row   = idx >> 3;
            int col16 = idx & 7;
            const __half* p = qkv + (tok0 + qt * 128 + row) * C3 + h * D + col16 * 8;
            uint4 v = *(const uint4*)p;
            __half2* hv = (__half2*)&v;
            hv[0] = __hmul2(hv[0], sc);
            hv[1] = __hmul2(hv[1], sc);
            hv[2] = __hmul2(hv[2], sc);
            hv[3] = __hmul2(hv[3], sc);
            *(uint4*)(Qs + row * ASTR + col16 * 8) = v;
        }
    }

    auto stage_kv = [&](int c) {
        uint32_t base = smBase + (uint32_t)Q_BYTES + (uint32_t)((c % 3) * AST_BYTES);
        int kt = c * 64;
        #pragma unroll
        for (int it = 0; it < 4; it++) {
            int idx   = t + it * 128;
            int row   = idx >> 3;
            int col16 = idx & 7;
            uint32_t soff = (uint32_t)(row * (ASTR * 2) + col16 * 16);
            const __half* kp = qkv + (tok0 + kt + row) * C3 + C + h * D + col16 * 8;
            cp_async16(base + soff, kp);
            cp_async16(base + (uint32_t)KV_BYTES + soff, kp + C);
        }
        cp_commit();
    };

    stage_kv(0);
    stage_kv(1);
    __syncthreads();

    uint32_t aq_off = (uint32_t)(((w * 32 + lrow + (lsel & 1) * 8) * ASTR + (lsel >> 1) * 8) * 2);
    uint32_t qf[2][4][4];
    #pragma unroll
    for (int mi = 0; mi < 2; mi++)
        #pragma unroll
        for (int ks = 0; ks < 4; ks++)
            ldsm_x4(qf[mi][ks][0], qf[mi][ks][1], qf[mi][ks][2], qf[mi][ks][3],
                    smBase + aq_off + (uint32_t)(mi * 16 * ASTR * 2) + (uint32_t)(ks * 32));

    float m[2][2], l[2][2];
    float oacc[2][8][4];
    #pragma unroll
    for (int mi = 0; mi < 2; mi++) {
        m[mi][0] = m[mi][1] = -1e30f;
        l[mi][0] = l[mi][1] = 0.f;
        #pragma unroll
        for (int nt = 0; nt < 8; nt++)
            #pragma unroll
            for (int r = 0; r < 4; r++) oacc[mi][nt][r] = 0.f;
    }

    uint32_t bn_off  = (uint32_t)(((lrow + (lsel >> 1) * 8) * ASTR + (lsel & 1) * 8) * 2);
    uint32_t vtr_off = (uint32_t)(((lrow + (lsel & 1) * 8) * ASTR + (lsel >> 1) * 8) * 2);

    for (int c = 0; c < NCHK; c++) {
        if (c + 1 < NCHK) cp_wait<1>(); else cp_wait<0>();
        __syncthreads();
        if (c + 2 < NCHK) stage_kv(c + 2);

        uint32_t stBase = smBase + (uint32_t)Q_BYTES + (uint32_t)((c % 3) * AST_BYTES);
        uint32_t KsB = stBase;
        uint32_t VsB = stBase + (uint32_t)KV_BYTES;

        float sacc[2][8][4];
        #pragma unroll
        for (int mi = 0; mi < 2; mi++)
            #pragma unroll
            for (int nt = 0; nt < 8; nt++)
                #pragma unroll
                for (int r = 0; r < 4; r++) sacc[mi][nt][r] = 0.f;

        #pragma unroll
        for (int ks = 0; ks < 4; ks++) {
            uint32_t bf[8][2];
            #pragma unroll
            for (int p = 0; p < 4; p++)
                ldsm_x4(bf[2*p][0], bf[2*p][1], bf[2*p+1][0], bf[2*p+1][1],
                        KsB + bn_off + (uint32_t)(p * 16 * ASTR * 2) + (uint32_t)(ks * 32));
            #pragma unroll
            for (int mi = 0; mi < 2; mi++)
                #pragma unroll
                for (int nt = 0; nt < 8; nt++)
                    mma_16n8k16(sacc[mi][nt], qf[mi][ks], bf[nt]);
        }

        #pragma unroll
        for (int mi = 0; mi < 2; mi++) {
            float r0 = -1e30f, r1 = -1e30f;
            #pragma unroll
            for (int nt = 0; nt < 8; nt++) {
                r0 = fmaxf(r0, fmaxf(sacc[mi][nt][0], sacc[mi][nt][1]));
                r1 = fmaxf(r1, fmaxf(sacc[mi][nt][2], sacc[mi][nt][3]));
            }
            r0 = fmaxf(r0, __shfl_xor_sync(0xffffffffu, r0, 1));
            r0 = fmaxf(r0, __shfl_xor_sync(0xffffffffu, r0, 2));
            r1 = fmaxf(r1, __shfl_xor_sync(0xffffffffu, r1, 1));
            r1 = fmaxf(r1, __shfl_xor_sync(0xffffffffu, r1, 2));
            float mn0 = fmaxf(m[mi][0], r0);
            float mn1 = fmaxf(m[mi][1], r1);
            float c0 = exp2f(m[mi][0] - mn0);
            float c1 = exp2f(m[mi][1] - mn1);
            m[mi][0] = mn0; m[mi][1] = mn1;
            l[mi][0] *= c0; l[mi][1] *= c1;
            #pragma unroll
            for (int nt = 0; nt < 8; nt++) {
                oacc[mi][nt][0] *= c0; oacc[mi][nt][1] *= c0;
                oacc[mi][nt][2] *= c1; oacc[mi][nt][3] *= c1;
            }
            #pragma unroll
            for (int nt = 0; nt < 8; nt++) {
                float p0 = exp2f(sacc[mi][nt][0] - mn0);
                float p1 = exp2f(sacc[mi][nt][1] - mn0);
                float p2 = exp2f(sacc[mi][nt][2] - mn1);
                float p3 = exp2f(sacc[mi][nt][3] - mn1);
                l[mi][0] += p0 + p1;
                l[mi][1] += p2 + p3;
                sacc[mi][nt][0] = p0; sacc[mi][nt][1] = p1;
                sacc[mi][nt][2] = p2; sacc[mi][nt][3] = p3;
            }
        }

        #pragma unroll
        for (int ks = 0; ks < 4; ks++) {
            uint32_t bf[8][2];
            #pragma unroll
            for (int p = 0; p < 4; p++)
                ldsm_x4_trans(bf[2*p][0], bf[2*p][1], bf[2*p+1][0], bf[2*p+1][1],
                              VsB + vtr_off + (uint32_t)(ks * 16 * ASTR * 2) + (uint32_t)(p * 32));
            uint32_t af[2][4];
            #pragma unroll
            for (int mi = 0; mi < 2; mi++) {
                af[mi][0] = pack_h2(sacc[mi][2*ks][0],   sacc[mi][2*ks][1]);
                af[mi][1] = pack_h2(sacc[mi][2*ks][2],   sacc[mi][2*ks][3]);
                af[mi][2] = pack_h2(sacc[mi][2*ks+1][0], sacc[mi][2*ks+1][1]);
                af[mi][3] = pack_h2(sacc[mi][2*ks+1][2], sacc[mi][2*ks+1][3]);
            }
            #pragma unroll
            for (int mi = 0; mi < 2; mi++)
                #pragma unroll
                for (int nt = 0; nt < 8; nt++)
                    mma_16n8k16(oacc[mi][nt], af[mi], bf[nt]);
        }
    }

    #pragma unroll
    for (int mi = 0; mi < 2; mi++) {
        float l0 = l[mi][0], l1 = l[mi][1];
        l0 += __shfl_xor_sync(0xffffffffu, l0, 1);
        l0 += __shfl_xor_sync(0xffffffffu, l0, 2);
        l1 += __shfl_xor_sync(0xffffffffu, l1, 1);
        l1 += __shfl_xor_sync(0xffffffffu, l1, 2);
        float i0 = 1.f / l0, i1 = 1.f / l1;
        int rlo = qt * 128 + w * 32 + mi * 16 + grp;
        __half* olo = out + (tok0 + rlo) * C + h * D;
        __half* ohi = out + (tok0 + rlo + 8) * C + h * D;
        #pragma unroll
        for (int nt = 0; nt < 8; nt++) {
            int col = nt * 8 + tg * 2;
            *(__half2*)(olo + col) = __floats2half2_rn(oacc[mi][nt][0] * i0,
                                                       oacc[mi][nt][1] * i0);
            *(__half2*)(ohi + col) = __floats2half2_rn(oacc[mi][nt][2] * i1,
                                                       oacc[mi][nt][3] * i1);
        }
    }
}

// ---------------------------------------------------------------------------
// Launch
// ---------------------------------------------------------------------------
extern "C" void kernel_launch(void* const* d_in, const int* in_sizes, int n_in,
                              void* d_out, int out_size)
{
    const float* x      = (const float*)d_in[0];
    const float* ln1_g  = (const float*)d_in[1];
    const float* ln1_b  = (const float*)d_in[2];
    const float* ln2_g  = (const float*)d_in[3];
    const float* ln2_b  = (const float*)d_in[4];
    const float* w_qkv  = (const float*)d_in[5];
    const float* w_proj = (const float*)d_in[6];
    const float* w1     = (const float*)d_in[7];
    const float* b1     = (const float*)d_in[8];
    const float* w2     = (const float*)d_in[9];
    const float* b2     = (const float*)d_in[10];
    float* out = (float*)d_out;

    __half* ln   = nullptr;  cudaGetSymbolAddress((void**)&ln,   g_ln);
    __half* qkv  = nullptr;  cudaGetSymbolAddress((void**)&qkv,  g_qkv);
    __half* attn = nullptr;  cudaGetSymbolAddress((void**)&attn, g_attn);
    __half* h1   = nullptr;  cudaGetSymbolAddress((void**)&h1,   g_h1);
    __half* wt   = nullptr;  cudaGetSymbolAddress((void**)&wt,   g_wt);

    cudaFuncSetAttribute(gemm_fp16<0, false, false, true >, cudaFuncAttributeMaxDynamicSharedMemorySize, GEMM_SMEM_BYTES);
    cudaFuncSetAttribute(gemm_fp16<0, false, true,  false>, cudaFuncAttributeMaxDynamicSharedMemorySize, GEMM_SMEM_BYTES);
    cudaFuncSetAttribute(gemm_fp16<1, true,  false, true >, cudaFuncAttributeMaxDynamicSharedMemorySize, GEMM_SMEM_BYTES);
    cudaFuncSetAttribute(gemm_fp16<0, true,  true,  false>, cudaFuncAttributeMaxDynamicSharedMemorySize, GEMM_SMEM_BYTES);
    cudaFuncSetAttribute(attn_mma_kernel, cudaFuncAttributeMaxDynamicSharedMemorySize, ATTN_SMEM_BYTES);

    // 0) weights transpose+convert AND LN1 (one launch, independent inputs)
    prep_kernel<<<PREP_GRID, 256>>>(w_qkv, w_proj, w1, w2, wt, x, ln1_g, ln1_b, ln);

    // 2) qkv = ln @ w_qkv (fp16 out)
    gemm_fp16<0, false, false, true><<<NPERS, 128, GEMM_SMEM_BYTES>>>(
        ln, wt + WT_QKV, nullptr, nullptr, qkv, BT, C3, C);

    // 3) attention (fp16 in/out)
    attn_mma_kernel<<<dim3(T / 128, H, 4), 128, ATTN_SMEM_BYTES>>>(qkv, attn);

    // 4) out = x + attn @ w_proj (fp32 out)
    gemm_fp16<0, false, true, false><<<NPERS, 128, GEMM_SMEM_BYTES>>>(
        attn, wt + WT_PROJ, nullptr, x, out, BT, C, C);

    // 5) LN2(out) -> ln (fp16)
    ln_kernel<<<BT, 256>>>(out, ln2_g, ln2_b, ln);

    // 6) h1 = gelu(ln @ w1 + b1) (fp16 out)
    gemm_fp16<1, true, false, true><<<NPERS, 128, GEMM_SMEM_BYTES>>>(
        ln, wt + WT_W1, b1, nullptr, h1, BT, DFF, C);

    // 7) out = out + h1 @ w2 + b2 (fp32 out)
    gemm_fp16<0, true, true, false><<<NPERS, 128, GEMM_SMEM_BYTES>>>(
        h1, wt + WT_W2, b2, out, out, BT, C, DFF);
}

// round 15
// speedup vs baseline: 1.0550x; 1.0550x over previous
#include <cuda_runtime.h>
#include <cuda_fp16.h>
#include <math.h>
#include <stdint.h>

// ---------------------------------------------------------------------------
// TransformerBlock: fp16 m16n8k16 mma.sync GEMMs (K-chunk 64, one barrier per
// chunk, 2-stage cp.async, R13 config) + fp16 flash attention (P-in-register,
// exp2 softmax). Merged wtr+ln1 prep launch.
// Shapes: B=4, T=2048 (BT=8192), C=1024, H=16, D=64, DFF=4096
// ---------------------------------------------------------------------------

#define BT   8192
#define C    1024
#define C3   3072
#define H    16
#define D    64
#define DFF  4096
#define T    2048
#define EPS  1e-5f

// Scratch (__device__ globals; no allocations allowed)
__device__ __half g_ln[BT * C];
__device__ __half g_qkv[BT * C3];
__device__ __half g_attn[BT * C];
__device__ __half g_h1[BT * DFF];
// fp16 TRANSPOSED weights: [N][K]
#define WT_QKV  0
#define WT_PROJ (WT_QKV + C * C3)
#define WT_W1   (WT_PROJ + C * C)
#define WT_W2   (WT_W1 + C * DFF)
#define WT_TOT  (WT_W2 + DFF * C)
__device__ __half g_wt[WT_TOT];

// ---------------------------------------------------------------------------
// Helpers
// ---------------------------------------------------------------------------
__device__ __forceinline__ uint32_t smem_u32(const void* p) {
    uint32_t a;
    asm("{ .reg .u64 t; cvta.to.shared.u64 t, %1; cvt.u32.u64 %0, t; }" : "=r"(a) : "l"(p));
    return a;
}
__device__ __forceinline__ void cp_async16(uint32_t dst, const void* src) {
    asm volatile("cp.async.ca.shared.global [%0], [%1], 16;" :: "r"(dst), "l"(src) : "memory");
}
__device__ __forceinline__ void cp_commit() {
    asm volatile("cp.async.commit_group;" ::: "memory");
}
template<int N>
__device__ __forceinline__ void cp_wait() {
    asm volatile("cp.async.wait_group %0;" :: "n"(N) : "memory");
}
__device__ __forceinline__ void ldsm_x4(uint32_t& r0, uint32_t& r1, uint32_t& r2, uint32_t& r3,
                                        uint32_t addr) {
    asm volatile("ldmatrix.sync.aligned.m8n8.x4.shared.b16 {%0,%1,%2,%3}, [%4];"
                 : "=r"(r0), "=r"(r1), "=r"(r2), "=r"(r3) : "r"(addr));
}
__device__ __forceinline__ void ldsm_x4_trans(uint32_t& r0, uint32_t& r1, uint32_t& r2, uint32_t& r3,
                                              uint32_t addr) {
    asm volatile("ldmatrix.sync.aligned.m8n8.x4.trans.shared.b16 {%0,%1,%2,%3}, [%4];"
                 : "=r"(r0), "=r"(r1), "=r"(r2), "=r"(r3) : "r"(addr));
}
__device__ __forceinline__ void mma_16n8k16(float* d, const uint32_t* a, const uint32_t* b) {
    asm volatile(
        "mma.sync.aligned.m16n8k16.row.col.f32.f16.f16.f32 "
        "{%0,%1,%2,%3}, {%4,%5,%6,%7}, {%8,%9}, {%0,%1,%2,%3};"
        : "+f"(d[0]), "+f"(d[1]), "+f"(d[2]), "+f"(d[3])
        : "r"(a[0]), "r"(a[1]), "r"(a[2]), "r"(a[3]), "r"(b[0]), "r"(b[1]));
}
__device__ __forceinline__ uint32_t pack_h2(float a, float b) {
    __half2 h = __floats2half2_rn(a, b);
    return *(uint32_t*)&h;
}
__device__ __forceinline__ float gelu_exact(float v) {
    return 0.5f * v * (1.0f + erff(v * 0.70710678118654752f));
}

// ---------------------------------------------------------------------------
// LayerNorm row body (shared by prep kernel and ln2 kernel)
// ---------------------------------------------------------------------------
__device__ __forceinline__ void ln_row(
    const float* __restrict__ x, const float* __restrict__ g,
    const float* __restrict__ beta, __half* __restrict__ out, int row, int t)
{
    const float* xr = x + (size_t)row * C;
    float4 xv = *(const float4*)(xr + t * 4);
    float s  = xv.x + xv.y + xv.z + xv.w;
    float s2 = xv.x * xv.x + xv.y * xv.y + xv.z * xv.z + xv.w * xv.w;
    #pragma unroll
    for (int o = 16; o > 0; o >>= 1) {
        s  += __shfl_xor_sync(0xffffffffu, s,  o);
        s2 += __shfl_xor_sync(0xffffffffu, s2, o);
    }
    __shared__ float ss[8], ss2[8];
    int w = t >> 5, lane = t & 31;
    if (lane == 0) { ss[w] = s; ss2[w] = s2; }
    __syncthreads();
    if (w == 0) {
        s  = (lane < 8) ? ss[lane]  : 0.f;
        s2 = (lane < 8) ? ss2[lane] : 0.f;
        #pragma unroll
        for (int o = 4; o > 0; o >>= 1) {
            s  += __shfl_xor_sync(0xffffffffu, s,  o);
            s2 += __shfl_xor_sync(0xffffffffu, s2, o);
        }
        if (lane == 0) { ss[0] = s; ss2[0] = s2; }
    }
    __syncthreads();
    float mu  = ss[0] * (1.0f / C);
    float var = ss2[0] * (1.0f / C) - mu * mu;
    float inv = rsqrtf(var + EPS);
    float4 gv = *(const float4*)(g + t * 4);
    float4 bv = *(const float4*)(beta + t * 4);
    __half2* o = (__half2*)(out + (size_t)row * C + t * 4);
    o[0] = __floats2half2_rn((xv.x - mu) * inv * gv.x + bv.x,
                             (xv.y - mu) * inv * gv.y + bv.y);
    o[1] = __floats2half2_rn((xv.z - mu) * inv * gv.z + bv.z,
                             (xv.w - mu) * inv * gv.w + bv.w);
}

__global__ __launch_bounds__(256) void ln_kernel(
    const float* __restrict__ x, const float* __restrict__ g,
    const float* __restrict__ beta, __half* __restrict__ out)
{
    ln_row(x, g, beta, out, blockIdx.x, threadIdx.x);
}

// ---------------------------------------------------------------------------
// Prep kernel: weight transpose+convert (blocks [0, WTR_GRID)) AND LN1
// (blocks [WTR_GRID, WTR_GRID+BT)). Independent inputs, both memory-bound.
// ---------------------------------------------------------------------------
#define WTR_GRID (768 + 256 + 1024 + 1024)
#define PREP_GRID (WTR_GRID + BT)

__global__ __launch_bounds__(256) void prep_kernel(
    const float* __restrict__ wqkv, const float* __restrict__ wproj,
    const float* __restrict__ w1, const float* __restrict__ w2,
    __half* __restrict__ wt,
    const float* __restrict__ x, const float* __restrict__ ln1_g,
    const float* __restrict__ ln1_b, __half* __restrict__ lnout)
{
    int b = blockIdx.x;
    int t = threadIdx.x;
    if (b >= WTR_GRID) {
        ln_row(x, ln1_g, ln1_b, lnout, b - WTR_GRID, t);
        return;
    }
    const float* in; __half* out; int K, N, local;
    if (b < 768)        { in = wqkv;  out = wt + WT_QKV;  K = C;   N = C3;  local = b; }
    else if (b < 1024)  { in = wproj; out = wt + WT_PROJ; K = C;   N = C;   local = b - 768; }
    else if (b < 2048)  { in = w1;    out = wt + WT_W1;   K = C;   N = DFF; local = b - 1024; }
    else                { in = w2;    out = wt + WT_W2;   K = DFF; N = C;   local = b - 2048; }
    int nX = N >> 6;
    int n0 = (local % nX) * 64, k0 = (local / nX) * 64;

    __shared__ float tile[64][65];
    #pragma unroll
    for (int it = 0; it < 4; it++) {
        int idx = t + it * 256;
        int kr = idx >> 4;
        int nc = (idx & 15) << 2;
        float4 v = *(const float4*)(in + (size_t)(k0 + kr) * N + n0 + nc);
        tile[kr][nc] = v.x; tile[kr][nc + 1] = v.y;
        tile[kr][nc + 2] = v.z; tile[kr][nc + 3] = v.w;
    }
    __syncthreads();
    #pragma unroll
    for (int it = 0; it < 2; it++) {
        int idx = t + it * 256;
        int nr = idx >> 3;
        int kc = (idx & 7) << 3;
        __half h[8];
        #pragma unroll
        for (int i = 0; i < 8; i++) h[i] = __float2half(tile[kc + i][nr]);
        *(uint4*)(out + (size_t)(n0 + nr) * K + k0 + kc) = *(uint4*)h;
    }
}

// ---------------------------------------------------------------------------
// fp16 mma.sync GEMM (R13 configuration): D = A @ Bt^T (+bias)(gelu)(+resid)
// CTA 128x128, 128 threads (4 warps 2x2), warp tile 64x64,
// K-chunk 64, 2-stage cp.async, ONE barrier per chunk, ldmatrix b16.
// ---------------------------------------------------------------------------
#define HSTR 72
#define TILE_BYTES (128 * HSTR * 2)
#define STAGE_BYTES (2 * TILE_BYTES)
#define GEMM_SMEM_BYTES (2 * STAGE_BYTES)

template<int ACT, bool BIAS, bool RESID, bool OUT_HALF>
__global__ __launch_bounds__(128, 2) void gemm_fp16(
    const __half* __restrict__ A, const __half* __restrict__ Bt,
    const float* __restrict__ bias, const float* __restrict__ resid,
    void* __restrict__ CoutV, int M, int N, int K)
{
    extern __shared__ char smem[];
    int t    = threadIdx.x;
    int lane = t & 31;
    int w    = t >> 5;
    int grp  = lane >> 2;
    int tg   = lane & 3;
    int bm = blockIdx.y * 128;
    int bn = blockIdx.x * 128;
    int wm = (w >> 1) * 64;
    int wn = (w & 1) * 64;

    uint32_t smemBase = smem_u32(smem);

    int lrow = lane & 7;
    int lsel = lane >> 3;
    uint32_t a_off = (uint32_t)(((wm + lrow + (lsel & 1) * 8) * HSTR + (lsel >> 1) * 8) * 2);
    uint32_t b_off = (uint32_t)(((wn + lrow + (lsel >> 1) * 8) * HSTR + (lsel & 1) * 8) * 2)
                   + (uint32_t)TILE_BYTES;

    float acc[4][8][4];
    #pragma unroll
    for (int mi = 0; mi < 4; mi++)
        #pragma unroll
        for (int ni = 0; ni < 8; ni++)
            #pragma unroll
            for (int r = 0; r < 4; r++) acc[mi][ni][r] = 0.f;

    const int NCH = K >> 6;

    auto load_chunk = [&](int c) {
        int buf = c & 1;
        uint32_t base = smemBase + (uint32_t)(buf * STAGE_BYTES);
        int k0 = c << 6;
        #pragma unroll
        for (int it = 0; it < 8; it++) {
            int idx   = t + it * 128;
            int row   = idx >> 3;
            int col16 = idx & 7;
            uint32_t soff = (uint32_t)(row * (HSTR * 2) + col16 * 16);
            cp_async16(base + soff,
                       A + (size_t)(bm + row) * K + k0 + col16 * 8);
            cp_async16(base + (uint32_t)TILE_BYTES + soff,
                       Bt + (size_t)(bn + row) * K + k0 + col16 * 8);
        }
        cp_commit();
    };

    load_chunk(0);

    for (int c = 0; c < NCH; c++) {
        cp_wait<0>();
        __syncthreads();
        if (c + 1 < NCH) load_chunk(c + 1);

        uint32_t base = smemBase + (uint32_t)((c & 1) * STAGE_BYTES);
        uint32_t aB = base + a_off;
        uint32_t bB = base + b_off;

        #pragma unroll
        for (int ks = 0; ks < 4; ks++) {
            uint32_t kOff = (uint32_t)(ks * 32);
            uint32_t af[4][4], bf[8][2];
            #pragma unroll
            for (int mi = 0; mi < 4; mi++)
                ldsm_x4(af[mi][0], af[mi][1], af[mi][2], af[mi][3],
                        aB + kOff + (uint32_t)(mi * 16 * HSTR * 2));
            #pragma unroll
            for (int p = 0; p < 4; p++)
                ldsm_x4(bf[2*p][0], bf[2*p][1], bf[2*p+1][0], bf[2*p+1][1],
                        bB + kOff + (uint32_t)(p * 16 * HSTR * 2));
            #pragma unroll
            for (int mi = 0; mi < 4; mi++)
                #pragma unroll
                for (int ni = 0; ni < 8; ni++)
                    mma_16n8k16(acc[mi][ni], af[mi], bf[ni]);
        }
    }

    #pragma unroll
    for (int mi = 0; mi < 4; mi++) {
        #pragma unroll
        for (int half = 0; half < 2; half++) {
            int row = bm + wm + mi * 16 + grp + half * 8;
            const float* rrow = RESID ? (resid + (size_t)row * N + bn) : nullptr;
            #pragma unroll
            for (int ni = 0; ni < 8; ni++) {
                int col = wn + ni * 8 + tg * 2;
                float v0 = acc[mi][ni][half * 2 + 0];
                float v1 = acc[mi][ni][half * 2 + 1];
                if (BIAS) {
                    float2 bb = *(const float2*)(bias + bn + col);
                    v0 += bb.x; v1 += bb.y;
                }
                if (ACT == 1) { v0 = gelu_exact(v0); v1 = gelu_exact(v1); }
                if (RESID) {
                    float2 rr = *(const float2*)(rrow + col);
                    v0 += rr.x; v1 += rr.y;
                }
                if (OUT_HALF) {
                    __half* orow = (__half*)CoutV + (size_t)row * N + bn;
                    *(__half2*)(orow + col) = __floats2half2_rn(v0, v1);
                } else {
                    float* orow = (float*)CoutV + (size_t)row * N + bn;
                    *(float2*)(orow + col) = make_float2(v0, v1);
                }
            }
        }
    }
}

// ---------------------------------------------------------------------------
// Flash attention, fp16 m16n8k16, exp2 softmax (Q pre-scaled 0.125*log2e).
// ---------------------------------------------------------------------------
#define ASTR 72
#define Q_BYTES   (128 * ASTR * 2)
#define KV_BYTES  (64 * ASTR * 2)
#define AST_BYTES (2 * KV_BYTES)
#define ATTN_SMEM_BYTES (Q_BYTES + 3 * AST_BYTES)

__global__ __launch_bounds__(128, 2) void attn_mma_kernel(
    const __half* __restrict__ qkv, __half* __restrict__ out)
{
    extern __shared__ char sm[];
    uint32_t smBase = smem_u32(sm);
    __half* Qs = (__half*)sm;

    int qt = blockIdx.x, h = blockIdx.y, b = blockIdx.z;
    int t = threadIdx.x, lane = t & 31, w = t >> 5;
    int grp = lane >> 2, tg = lane & 3;
    int lrow = lane & 7, lsel = lane >> 3;

    const size_t tok0 = (size_t)b * T;
    const int NCHK = T / 64;

    {
        __half2 sc = __float2half2_rn(0.18033688f);   // 0.125 * log2(e)
        #pragma unroll
        for (int it = 0; it < 8; it++) {
            int idx   = t + it * 128;
            int row   = idx >> 3;
            int col16 = idx & 7;
            const __half* p = qkv + (tok0 + qt * 128 + row) * C3 + h * D + col16 * 8;
            uint4 v = *(const uint4*)p;
            __half2* hv = (__half2*)&v;
            hv[0] = __hmul2(hv[0], sc);
            hv[1] = __hmul2(hv[1], sc);
            hv[2] = __hmul2(hv[2], sc);
            hv[3] = __hmul2(hv[3], sc);
            *(uint4*)(Qs + row * ASTR + col16 * 8) = v;
        }
    }

    auto stage_kv = [&](int c) {
        uint32_t base = smBase + (uint32_t)Q_BYTES + (uint32_t)((c % 3) * AST_BYTES);
        int kt = c * 64;
        #pragma unroll
        for (int it = 0; it < 4; it++) {
            int idx   = t + it * 128;
            int row   = idx >> 3;
            int col16 = idx & 7;
            uint32_t soff = (uint32_t)(row * (ASTR * 2) + col16 * 16);
            const __half* kp = qkv + (tok0 + kt + row) * C3 + C + h * D + col16 * 8;
            cp_async16(base + soff, kp);
            cp_async16(base + (uint32_t)KV_BYTES + soff, kp + C);
        }
        cp_commit();
    };

    stage_kv(0);
    stage_kv(1);
    __syncthreads();

    uint32_t aq_off = (uint32_t)(((w * 32 + lrow + (lsel & 1) * 8) * ASTR + (lsel >> 1) * 8) * 2);
    uint32_t qf[2][4][4];
    #pragma unroll
    for (int mi = 0; mi < 2; mi++)
        #pragma unroll
        for (int ks = 0; ks < 4; ks++)
            ldsm_x4(qf[mi][ks][0], qf[mi][ks][1], qf[mi][ks][2], qf[mi][ks][3],
                    smBase + aq_off + (uint32_t)(mi * 16 * ASTR * 2) + (uint32_t)(ks * 32));

    float m[2][2], l[2][2];
    float oacc[2][8][4];
    #pragma unroll
    for (int mi = 0; mi < 2; mi++) {
        m[mi][0] = m[mi][1] = -1e30f;
        l[mi][0] = l[mi][1] = 0.f;
        #pragma unroll
        for (int nt = 0; nt < 8; nt++)
            #pragma unroll
            for (int r = 0; r < 4; r++) oacc[mi][nt][r] = 0.f;
    }

    uint32_t bn_off  = (uint32_t)(((lrow + (lsel >> 1) * 8) * ASTR + (lsel & 1) * 8) * 2);
    uint32_t vtr_off = (uint32_t)(((lrow + (lsel & 1) * 8) * ASTR + (lsel >> 1) * 8) * 2);

    for (int c = 0; c < NCHK; c++) {
        if (c + 1 < NCHK) cp_wait<1>(); else cp_wait<0>();
        __syncthreads();
        if (c + 2 < NCHK) stage_kv(c + 2);

        uint32_t stBase = smBase + (uint32_t)Q_BYTES + (uint32_t)((c % 3) * AST_BYTES);
        uint32_t KsB = stBase;
        uint32_t VsB = stBase + (uint32_t)KV_BYTES;

        float sacc[2][8][4];
        #pragma unroll
        for (int mi = 0; mi < 2; mi++)
            #pragma unroll
            for (int nt = 0; nt < 8; nt++)
                #pragma unroll
                for (int r = 0; r < 4; r++) sacc[mi][nt][r] = 0.f;

        #pragma unroll
        for (int ks = 0; ks < 4; ks++) {
            uint32_t bf[8][2];
            #pragma unroll
            for (int p = 0; p < 4; p++)
                ldsm_x4(bf[2*p][0], bf[2*p][1], bf[2*p+1][0], bf[2*p+1][1],
                        KsB + bn_off + (uint32_t)(p * 16 * ASTR * 2) + (uint32_t)(ks * 32));
            #pragma unroll
            for (int mi = 0; mi < 2; mi++)
                #pragma unroll
                for (int nt = 0; nt < 8; nt++)
                    mma_16n8k16(sacc[mi][nt], qf[mi][ks], bf[nt]);
        }

        #pragma unroll
        for (int mi = 0; mi < 2; mi++) {
            float r0 = -1e30f, r1 = -1e30f;
            #pragma unroll
            for (int nt = 0; nt < 8; nt++) {
                r0 = fmaxf(r0, fmaxf(sacc[mi][nt][0], sacc[mi][nt][1]));
                r1 = fmaxf(r1, fmaxf(sacc[mi][nt][2], sacc[mi][nt][3]));
            }
            r0 = fmaxf(r0, __shfl_xor_sync(0xffffffffu, r0, 1));
            r0 = fmaxf(r0, __shfl_xor_sync(0xffffffffu, r0, 2));
            r1 = fmaxf(r1, __shfl_xor_sync(0xffffffffu, r1, 1));
            r1 = fmaxf(r1, __shfl_xor_sync(0xffffffffu, r1, 2));
            float mn0 = fmaxf(m[mi][0], r0);
            float mn1 = fmaxf(m[mi][1], r1);
            float c0 = exp2f(m[mi][0] - mn0);
            float c1 = exp2f(m[mi][1] - mn1);
            m[mi][0] = mn0; m[mi][1] = mn1;
            l[mi][0] *= c0; l[mi][1] *= c1;
            #pragma unroll
            for (int nt = 0; nt < 8; nt++) {
                oacc[mi][nt][0] *= c0; oacc[mi][nt][1] *= c0;
                oacc[mi][nt][2] *= c1; oacc[mi][nt][3] *= c1;
            }
            #pragma unroll
            for (int nt = 0; nt < 8; nt++) {
                float p0 = exp2f(sacc[mi][nt][0] - mn0);
                float p1 = exp2f(sacc[mi][nt][1] - mn0);
                float p2 = exp2f(sacc[mi][nt][2] - mn1);
                float p3 = exp2f(sacc[mi][nt][3] - mn1);
                l[mi][0] += p0 + p1;
                l[mi][1] += p2 + p3;
                sacc[mi][nt][0] = p0; sacc[mi][nt][1] = p1;
                sacc[mi][nt][2] = p2; sacc[mi][nt][3] = p3;
            }
        }

        #pragma unroll
        for (int ks = 0; ks < 4; ks++) {
            uint32_t bf[8][2];
            #pragma unroll
            for (int p = 0; p < 4; p++)
                ldsm_x4_trans(bf[2*p][0], bf[2*p][1], bf[2*p+1][0], bf[2*p+1][1],
                              VsB + vtr_off + (uint32_t)(ks * 16 * ASTR * 2) + (uint32_t)(p * 32));
            uint32_t af[2][4];
            #pragma unroll
            for (int mi = 0; mi < 2; mi++) {
                af[mi][0] = pack_h2(sacc[mi][2*ks][0],   sacc[mi][2*ks][1]);
                af[mi][1] = pack_h2(sacc[mi][2*ks][2],   sacc[mi][2*ks][3]);
                af[mi][2] = pack_h2(sacc[mi][2*ks+1][0], sacc[mi][2*ks+1][1]);
                af[mi][3] = pack_h2(sacc[mi][2*ks+1][2], sacc[mi][2*ks+1][3]);
            }
            #pragma unroll
            for (int mi = 0; mi < 2; mi++)
                #pragma unroll
                for (int nt = 0; nt < 8; nt++)
                    mma_16n8k16(oacc[mi][nt], af[mi], bf[nt]);
        }
    }

    #pragma unroll
    for (int mi = 0; mi < 2; mi++) {
        float l0 = l[mi][0], l1 = l[mi][1];
        l0 += __shfl_xor_sync(0xffffffffu, l0, 1);
        l0 += __shfl_xor_sync(0xffffffffu, l0, 2);
        l1 += __shfl_xor_sync(0xffffffffu, l1, 1);
        l1 += __shfl_xor_sync(0xffffffffu, l1, 2);
        float i0 = 1.f / l0, i1 = 1.f / l1;
        int rlo = qt * 128 + w * 32 + mi * 16 + grp;
        __half* olo = out + (tok0 + rlo) * C + h * D;
        __half* ohi = out + (tok0 + rlo + 8) * C + h * D;
        #pragma unroll
        for (int nt = 0; nt < 8; nt++) {
            int col = nt * 8 + tg * 2;
            *(__half2*)(olo + col) = __floats2half2_rn(oacc[mi][nt][0] * i0,
                                                       oacc[mi][nt][1] * i0);
            *(__half2*)(ohi + col) = __floats2half2_rn(oacc[mi][nt][2] * i1,
                                                       oacc[mi][nt][3] * i1);
        }
    }
}

// ---------------------------------------------------------------------------
// Launch
// ---------------------------------------------------------------------------
extern "C" void kernel_launch(void* const* d_in, const int* in_sizes, int n_in,
                              void* d_out, int out_size)
{
    const float* x      = (const float*)d_in[0];
    const float* ln1_g  = (const float*)d_in[1];
    const float* ln1_b  = (const float*)d_in[2];
    const float* ln2_g  = (const float*)d_in[3];
    const float* ln2_b  = (const float*)d_in[4];
    const float* w_qkv  = (const float*)d_in[5];
    const float* w_proj = (const float*)d_in[6];
    const float* w1     = (const float*)d_in[7];
    const float* b1     = (const float*)d_in[8];
    const float* w2     = (const float*)d_in[9];
    const float* b2     = (const float*)d_in[10];
    float* out = (float*)d_out;

    __half* ln   = nullptr;  cudaGetSymbolAddress((void**)&ln,   g_ln);
    __half* qkv  = nullptr;  cudaGetSymbolAddress((void**)&qkv,  g_qkv);
    __half* attn = nullptr;  cudaGetSymbolAddress((void**)&attn, g_attn);
    __half* h1   = nullptr;  cudaGetSymbolAddress((void**)&h1,   g_h1);
    __half* wt   = nullptr;  cudaGetSymbolAddress((void**)&wt,   g_wt);

    cudaFuncSetAttribute(gemm_fp16<0, false, false, true >, cudaFuncAttributeMaxDynamicSharedMemorySize, GEMM_SMEM_BYTES);
    cudaFuncSetAttribute(gemm_fp16<0, false, true,  false>, cudaFuncAttributeMaxDynamicSharedMemorySize, GEMM_SMEM_BYTES);
    cudaFuncSetAttribute(gemm_fp16<1, true,  false, true >, cudaFuncAttributeMaxDynamicSharedMemorySize, GEMM_SMEM_BYTES);
    cudaFuncSetAttribute(gemm_fp16<0, true,  true,  false>, cudaFuncAttributeMaxDynamicSharedMemorySize, GEMM_SMEM_BYTES);
    cudaFuncSetAttribute(attn_mma_kernel, cudaFuncAttributeMaxDynamicSharedMemorySize, ATTN_SMEM_BYTES);

    // 0) weights transpose+convert AND LN1 (one launch, independent inputs)
    prep_kernel<<<PREP_GRID, 256>>>(w_qkv, w_proj, w1, w2, wt, x, ln1_g, ln1_b, ln);

    // 2) qkv = ln @ w_qkv (fp16 out)
    gemm_fp16<0, false, false, true><<<dim3(C3 / 128, BT / 128), 128, GEMM_SMEM_BYTES>>>(
        ln, wt + WT_QKV, nullptr, nullptr, qkv, BT, C3, C);

    // 3) attention (fp16 in/out)
    attn_mma_kernel<<<dim3(T / 128, H, 4), 128, ATTN_SMEM_BYTES>>>(qkv, attn);

    // 4) out = x + attn @ w_proj (fp32 out)
    gemm_fp16<0, false, true, false><<<dim3(C / 128, BT / 128), 128, GEMM_SMEM_BYTES>>>(
        attn, wt + WT_PROJ, nullptr, x, out, BT, C, C);

    // 5) LN2(out) -> ln (fp16)
    ln_kernel<<<BT, 256>>>(out, ln2_g, ln2_b, ln);

    // 6) h1 = gelu(ln @ w1 + b1) (fp16 out)
    gemm_fp16<1, true, false, true><<<dim3(DFF / 128, BT / 128), 128, GEMM_SMEM_BYTES>>>(
        ln, wt + WT_W1, b1, nullptr, h1, BT, DFF, C);

    // 7) out = out + h1 @ w2 + b2 (fp32 out)
    gemm_fp16<0, true, true, false><<<dim3(C / 128, BT / 128), 128, GEMM_SMEM_BYTES>>>(
        h1, wt + WT_W2, b2, out, out, BT, C, DFF);
}